// round 14
// baseline (speedup 1.0000x reference)
#include <cuda_runtime.h>
#include <cuda_fp16.h>
#include <cstdint>

#define B_ 8
#define C_ 256
#define H_ 128
#define W_ 128
#define HW_ (H_*W_)            // 16384
#define K_ 1280
#define O_ 256

#define NEG_INF __int_as_float(0xff800000)

// ONE-BATCH fp16 scratch (42 MB total) -> stays L2-resident across the run.
__device__ __half g_x16[C_*HW_];
__device__ __half g_dir16[4][C_*HW_];
__device__ __half g_wT16[K_*O_];

// ------------------------------------------------------------------
// helpers
// ------------------------------------------------------------------
__device__ __forceinline__ uint32_t smem_u32(const void* p) {
    return (uint32_t)__cvta_generic_to_shared(p);
}
__device__ __forceinline__ void cp16(uint32_t s, const void* g) {
    asm volatile("cp.async.cg.shared.global [%0], [%1], 16;\n" :: "r"(s), "l"(g));
}
__device__ __forceinline__ void ldsm_x4_t(uint32_t& d0, uint32_t& d1,
                                          uint32_t& d2, uint32_t& d3, uint32_t a) {
    asm volatile("ldmatrix.sync.aligned.m8n8.x4.trans.shared.b16 {%0,%1,%2,%3},[%4];\n"
                 : "=r"(d0), "=r"(d1), "=r"(d2), "=r"(d3) : "r"(a));
}
__device__ __forceinline__ void mma_f16(float* d, const uint32_t* a, const uint32_t* b) {
    asm volatile(
        "mma.sync.aligned.m16n8k16.row.col.f32.f16.f16.f32 "
        "{%0,%1,%2,%3},{%4,%5,%6,%7},{%8,%9},{%0,%1,%2,%3};"
        : "+f"(d[0]), "+f"(d[1]), "+f"(d[2]), "+f"(d[3])
        : "r"(a[0]), "r"(a[1]), "r"(a[2]), "r"(a[3]), "r"(b[0]), "r"(b[1]));
}
__device__ __forceinline__ uint32_t h2u(__half2 h) {
    return *reinterpret_cast<uint32_t*>(&h);
}
// streaming fp32 store (evict-first) for GEMM output (never re-read)
__device__ __forceinline__ void stcs_f(void* p, float v) {
    asm volatile("st.global.cs.f32 [%0], %1;" :: "l"(p), "f"(v) : "memory");
}

// ------------------------------------------------------------------
// kernel 0: transpose conv_w [O][K] -> wT16 [K][O]
// ------------------------------------------------------------------
__global__ void k_wt(const float* __restrict__ w) {
    int idx = blockIdx.x * 256 + threadIdx.x;
    if (idx < K_*O_) {
        int o = idx / K_;
        int k = idx - o*K_;
        g_wT16[k*O_ + o] = __float2half_rn(w[idx]);
    }
}

// ------------------------------------------------------------------
// kernel 1: all 4 directional maxes + x16 for ONE batch -> L2-resident scratch.
// fp16 plane in smem (cvt monotone: fp16 scans == fp32 scans + cvt, bit-exact).
// warps 0-1 H-prefix, 2-3 H-suffix, 4-7 W-scans (2 rows in flight).
// x read with __ldcs (streaming); scratch stores NORMAL (want L2 retention).
// ------------------------------------------------------------------
#define SP_LD 132   // halves per smem row (264B)

__global__ void __launch_bounds__(256) k_dir(const float* __restrict__ x, int b) {
    __shared__ __half sp[H_*SP_LD];
    int plane = blockIdx.x;                         // 0..C_-1
    const float* src = x + (size_t)(b*C_ + plane)*HW_;
    __half* x16 = g_x16 + (size_t)plane*HW_;
    int tid = threadIdx.x;

    // ---- load: streaming float4 -> fp16 smem + fp16 scratch copy ----
    #pragma unroll
    for (int i = 0; i < 16; ++i) {
        int c = tid + i*256;               // float4 index 0..4095
        int h = c >> 5, f4 = c & 31;
        float4 v = __ldcs(reinterpret_cast<const float4*>(src) + c);
        __half2 a = __floats2half2_rn(v.x, v.y);
        __half2 bb = __floats2half2_rn(v.z, v.w);
        uint2 u = make_uint2(h2u(a), h2u(bb));
        *reinterpret_cast<uint2*>(x16 + (size_t)c*4) = u;
        *reinterpret_cast<uint2*>(sp + h*SP_LD + f4*4) = u;
    }
    __syncthreads();

    int warp = tid >> 5, lane = tid & 31;
    const __half2 ninf2 = __floats2half2_rn(NEG_INF, NEG_INF);

    if (warp < 2) {
        int t = tid;                       // 0..63, column pair
        __half* d0 = g_dir16[0] + (size_t)plane*HW_;
        __half2 m = ninf2;
        #pragma unroll 8
        for (int h = 0; h < H_; ++h) {
            m = __hmax2(m, *reinterpret_cast<__half2*>(sp + h*SP_LD + 2*t));
            *reinterpret_cast<__half2*>(d0 + h*W_ + 2*t) = m;
        }
    } else if (warp < 4) {
        int t = tid - 64;
        __half* d1 = g_dir16[1] + (size_t)plane*HW_;
        __half2 m = ninf2;
        #pragma unroll 8
        for (int h = H_-1; h >= 0; --h) {
            m = __hmax2(m, *reinterpret_cast<__half2*>(sp + h*SP_LD + 2*t));
            *reinterpret_cast<__half2*>(d1 + h*W_ + 2*t) = m;
        }
    } else {
        // W-scans: warp handles 32 rows, two rows in flight per iteration
        __half* d2 = g_dir16[2] + (size_t)plane*HW_;
        __half* d3 = g_dir16[3] + (size_t)plane*HW_;
        int hbase = (warp - 4)*32;
        for (int r = 0; r < 16; ++r) {
            int ha = hbase + r, hb = hbase + 16 + r;
            uint2 ua = *reinterpret_cast<uint2*>(sp + ha*SP_LD + 4*lane);
            uint2 ub = *reinterpret_cast<uint2*>(sp + hb*SP_LD + 4*lane);
            float2 a0 = __half22float2(*reinterpret_cast<__half2*>(&ua.x));
            float2 a1 = __half22float2(*reinterpret_cast<__half2*>(&ua.y));
            float2 b0 = __half22float2(*reinterpret_cast<__half2*>(&ub.x));
            float2 b1 = __half22float2(*reinterpret_cast<__half2*>(&ub.y));

            // prefix, both rows interleaved
            float pa0 = a0.x, pa1 = fmaxf(a0.y,pa0), pa2 = fmaxf(a1.x,pa1), pa3 = fmaxf(a1.y,pa2);
            float pb0 = b0.x, pb1 = fmaxf(b0.y,pb0), pb2 = fmaxf(b1.x,pb1), pb3 = fmaxf(b1.y,pb2);
            float aga = pa3, agb = pb3;
            #pragma unroll
            for (int d = 1; d < 32; d <<= 1) {
                float ta = __shfl_up_sync(0xffffffffu, aga, d);
                float tb = __shfl_up_sync(0xffffffffu, agb, d);
                if (lane >= d) { aga = fmaxf(aga, ta); agb = fmaxf(agb, tb); }
            }
            float pva = __shfl_up_sync(0xffffffffu, aga, 1);
            float pvb = __shfl_up_sync(0xffffffffu, agb, 1);
            if (lane == 0) { pva = NEG_INF; pvb = NEG_INF; }
            {
                __half2 A0 = __floats2half2_rn(fmaxf(pa0,pva), fmaxf(pa1,pva));
                __half2 A1 = __floats2half2_rn(fmaxf(pa2,pva), fmaxf(pa3,pva));
                __half2 B0 = __floats2half2_rn(fmaxf(pb0,pvb), fmaxf(pb1,pvb));
                __half2 B1 = __floats2half2_rn(fmaxf(pb2,pvb), fmaxf(pb3,pvb));
                *reinterpret_cast<uint2*>(d2 + ha*W_ + 4*lane) = make_uint2(h2u(A0), h2u(A1));
                *reinterpret_cast<uint2*>(d2 + hb*W_ + 4*lane) = make_uint2(h2u(B0), h2u(B1));
            }

            // suffix, both rows interleaved
            float sa3 = a1.y, sa2 = fmaxf(a1.x,sa3), sa1 = fmaxf(a0.y,sa2), sa0 = fmaxf(a0.x,sa1);
            float sb3 = b1.y, sb2 = fmaxf(b1.x,sb3), sb1 = fmaxf(b0.y,sb2), sb0 = fmaxf(b0.x,sb1);
            float ag2a = sa0, ag2b = sb0;
            #pragma unroll
            for (int d = 1; d < 32; d <<= 1) {
                float ta = __shfl_down_sync(0xffffffffu, ag2a, d);
                float tb = __shfl_down_sync(0xffffffffu, ag2b, d);
                if (lane + d < 32) { ag2a = fmaxf(ag2a, ta); ag2b = fmaxf(ag2b, tb); }
            }
            float nxa = __shfl_down_sync(0xffffffffu, ag2a, 1);
            float nxb = __shfl_down_sync(0xffffffffu, ag2b, 1);
            if (lane == 31) { nxa = NEG_INF; nxb = NEG_INF; }
            {
                __half2 A0 = __floats2half2_rn(fmaxf(sa0,nxa), fmaxf(sa1,nxa));
                __half2 A1 = __floats2half2_rn(fmaxf(sa2,nxa), fmaxf(sa3,nxa));
                __half2 B0 = __floats2half2_rn(fmaxf(sb0,nxb), fmaxf(sb1,nxb));
                __half2 B1 = __floats2half2_rn(fmaxf(sb2,nxb), fmaxf(sb3,nxb));
                *reinterpret_cast<uint2*>(d3 + ha*W_ + 4*lane) = make_uint2(h2u(A0), h2u(A1));
                *reinterpret_cast<uint2*>(d3 + hb*W_ + 4*lane) = make_uint2(h2u(B0), h2u(B1));
            }
        }
    }
}

// ------------------------------------------------------------------
// kernel 2: fp16 GEMM for ONE batch (A-reads hit L2-resident scratch).
// BM=128 pixels, BN=256 outs, BK=32, 256 threads, warp tile 64x64, 3 stages.
// Output stores streaming (.cs) to protect scratch residency.
// ------------------------------------------------------------------
#define BM 128
#define BN 256
#define BK 32
#define STAGES 3
#define SA_LD 136
#define SB_LD 264
#define STG_HALVES (BK*SA_LD + BK*SB_LD)
#define GEMM_SMEM (STAGES*STG_HALVES*2)   // 76800 B

__global__ void __launch_bounds__(256, 1) k_gemm(const float* __restrict__ bias,
                                                 float* __restrict__ out, int b) {
    extern __shared__ __half sm[];

    int tid  = threadIdx.x;
    int lane = tid & 31, warp = tid >> 5;
    int wm = warp >> 2, wn = warp & 3;
    int grp = lane >> 2, tig = lane & 3;
    int lr = lane & 7, lg = lane >> 3;

    int pixbase = blockIdx.x * BM;

    const __half* srcs[5] = { g_x16, g_dir16[0], g_dir16[1], g_dir16[2], g_dir16[3] };

    auto load_tile = [&](int kt, int st) {
        int region = kt >> 3;
        int c0 = (kt & 7) * BK;
        const __half* aptr = srcs[region] + (size_t)c0*HW_ + pixbase;
        const __half* bptr = g_wT16 + (size_t)(kt*BK)*O_;
        __half* sa = sm + st*STG_HALVES;
        __half* sb = sa + BK*SA_LD;
        #pragma unroll
        for (int i = 0; i < 2; ++i) {
            int c  = tid + i*256;
            int kr = c >> 4, cc = c & 15;
            cp16(smem_u32(sa + kr*SA_LD + cc*8), aptr + (size_t)kr*HW_ + cc*8);
        }
        #pragma unroll
        for (int i = 0; i < 4; ++i) {
            int c  = tid + i*256;
            int kr = c >> 5, cc = c & 31;
            cp16(smem_u32(sb + kr*SB_LD + cc*8), bptr + kr*O_ + cc*8);
        }
        asm volatile("cp.async.commit_group;\n" ::: "memory");
    };

    float acc[4][8][4];
    #pragma unroll
    for (int i = 0; i < 4; ++i)
        #pragma unroll
        for (int j = 0; j < 8; ++j)
            #pragma unroll
            for (int r = 0; r < 4; ++r) acc[i][j][r] = 0.f;

    load_tile(0, 0);
    load_tile(1, 1);

    for (int kt = 0; kt < 40; ++kt) {
        int cur = kt % STAGES;
        if (kt + 2 < 40) {
            load_tile(kt + 2, (kt + 2) % STAGES);
            asm volatile("cp.async.wait_group 2;\n" ::: "memory");
        } else {
            asm volatile("cp.async.wait_group %0;\n" :: "n"(0) : "memory");
        }
        __syncthreads();

        uint32_t saU = smem_u32(sm + cur*STG_HALVES);
        uint32_t sbU = saU + BK*SA_LD*2;

        uint32_t af[2][4][4];
        uint32_t bf[2][8][2];
        #pragma unroll
        for (int s = 0; s < 2; ++s) {
            int k0 = s*16;
            {
                int krow = k0 + lr + ((lg & 2) << 2);
                int cofs = (lg & 1) << 3;
                #pragma unroll
                for (int mf = 0; mf < 4; ++mf) {
                    int m0 = wm*64 + mf*16;
                    uint32_t a = saU + (uint32_t)(krow*SA_LD + m0 + cofs)*2;
                    ldsm_x4_t(af[s][mf][0], af[s][mf][1], af[s][mf][2], af[s][mf][3], a);
                }
            }
            {
                int krow = k0 + lr + ((lg & 1) << 3);
                int cofs = (lg >> 1) << 3;
                #pragma unroll
                for (int jp = 0; jp < 4; ++jp) {
                    int nj = wn*64 + jp*16;
                    uint32_t a = sbU + (uint32_t)(krow*SB_LD + nj + cofs)*2;
                    ldsm_x4_t(bf[s][2*jp][0], bf[s][2*jp][1],
                              bf[s][2*jp+1][0], bf[s][2*jp+1][1], a);
                }
            }
        }
        #pragma unroll
        for (int s = 0; s < 2; ++s)
            #pragma unroll
            for (int mf = 0; mf < 4; ++mf)
                #pragma unroll
                for (int nf = 0; nf < 8; ++nf)
                    mma_f16(acc[mf][nf], af[s][mf], bf[s][nf]);
        __syncthreads();
    }

    float* outb = out + (size_t)b * O_ * HW_;
    #pragma unroll
    for (int nf = 0; nf < 8; ++nf) {
        int o = wn*64 + nf*8 + tig*2;
        float bv0 = bias[o], bv1 = bias[o+1];
        #pragma unroll
        for (int mf = 0; mf < 4; ++mf) {
            int m = pixbase + wm*64 + mf*16 + grp;
            stcs_f(outb + (size_t)o*HW_ + m,         acc[mf][nf][0] + bv0);
            stcs_f(outb + (size_t)(o+1)*HW_ + m,     acc[mf][nf][1] + bv1);
            stcs_f(outb + (size_t)o*HW_ + m + 8,     acc[mf][nf][2] + bv0);
            stcs_f(outb + (size_t)(o+1)*HW_ + m + 8, acc[mf][nf][3] + bv1);
        }
    }
}

// ------------------------------------------------------------------
// launch: strictly serial on the default stream. Per batch: dir(b) fills the
// L2-resident scratch, gemm(b) consumes it. No streams, no events.
// ------------------------------------------------------------------
extern "C" void kernel_launch(void* const* d_in, const int* in_sizes, int n_in,
                              void* d_out, int out_size) {
    (void)in_sizes; (void)n_in; (void)out_size;
    const float* x    = (const float*)d_in[0];
    const float* w    = (const float*)d_in[1];
    const float* bias = (const float*)d_in[2];
    float* out = (float*)d_out;

    cudaFuncSetAttribute(k_gemm, cudaFuncAttributeMaxDynamicSharedMemorySize, GEMM_SMEM);

    k_wt<<<(K_*O_ + 255)/256, 256>>>(w);
    for (int b = 0; b < B_; ++b) {
        k_dir<<<C_, 256>>>(x, b);
        k_gemm<<<HW_/BM, 256, GEMM_SMEM>>>(bias, out, b);
    }
}

// round 15
// speedup vs baseline: 1.4874x; 1.4874x over previous
#include <cuda_runtime.h>
#include <cuda_fp16.h>
#include <cstdint>

#define B_ 8
#define C_ 256
#define H_ 128
#define W_ 128
#define HW_ (H_*W_)            // 16384
#define NPLANE (B_*C_)         // 2048
#define K_ 1280
#define O_ 256

#define NEG_INF __int_as_float(0xff800000)

// fp16 scratch: x copy + 4 directional-max tensors + transposed weights.
__device__ __half g_x16[NPLANE*HW_];
__device__ __half g_dir16[4][NPLANE*HW_];
__device__ __half g_wT16[K_*O_];

// ------------------------------------------------------------------
// helpers
// ------------------------------------------------------------------
__device__ __forceinline__ uint32_t smem_u32(const void* p) {
    return (uint32_t)__cvta_generic_to_shared(p);
}
__device__ __forceinline__ void cp16(uint32_t s, const void* g) {
    asm volatile("cp.async.cg.shared.global [%0], [%1], 16;\n" :: "r"(s), "l"(g));
}
__device__ __forceinline__ void ldsm_x4_t(uint32_t& d0, uint32_t& d1,
                                          uint32_t& d2, uint32_t& d3, uint32_t a) {
    asm volatile("ldmatrix.sync.aligned.m8n8.x4.trans.shared.b16 {%0,%1,%2,%3},[%4];\n"
                 : "=r"(d0), "=r"(d1), "=r"(d2), "=r"(d3) : "r"(a));
}
__device__ __forceinline__ void mma_f16(float* d, const uint32_t* a, const uint32_t* b) {
    asm volatile(
        "mma.sync.aligned.m16n8k16.row.col.f32.f16.f16.f32 "
        "{%0,%1,%2,%3},{%4,%5,%6,%7},{%8,%9},{%0,%1,%2,%3};"
        : "+f"(d[0]), "+f"(d[1]), "+f"(d[2]), "+f"(d[3])
        : "r"(a[0]), "r"(a[1]), "r"(a[2]), "r"(a[3]), "r"(b[0]), "r"(b[1]));
}
__device__ __forceinline__ uint32_t h2u(__half2 h) {
    return *reinterpret_cast<uint32_t*>(&h);
}

// ------------------------------------------------------------------
// kernel 0: transpose conv_w [O][K] -> wT16 [K][O]
// ------------------------------------------------------------------
__global__ void k_wt(const float* __restrict__ w) {
    int idx = blockIdx.x * 256 + threadIdx.x;
    if (idx < K_*O_) {
        int o = idx / K_;
        int k = idx - o*K_;
        g_wT16[k*O_ + o] = __float2half_rn(w[idx]);
    }
}

// ------------------------------------------------------------------
// kernel 1: all 4 directional maxes + x16, one plane per CTA, full grid
// (R12-proven: fp16 plane in smem; warps 0-1 H-prefix, 2-3 H-suffix,
//  4-7 W-scans; plain stores).
// ------------------------------------------------------------------
#define SP_LD 132   // halves per smem row (264B)

__global__ void __launch_bounds__(256) k_dir(const float* __restrict__ x) {
    __shared__ __half sp[H_*SP_LD];
    int plane = blockIdx.x;
    const float* src = x + (size_t)plane*HW_;
    __half* x16 = g_x16 + (size_t)plane*HW_;
    int tid = threadIdx.x;

    #pragma unroll
    for (int i = 0; i < 16; ++i) {
        int c = tid + i*256;               // float4 index 0..4095
        int h = c >> 5, f4 = c & 31;
        float4 v = __ldg(reinterpret_cast<const float4*>(src) + c);
        __half2 a = __floats2half2_rn(v.x, v.y);
        __half2 b = __floats2half2_rn(v.z, v.w);
        uint2 u = make_uint2(h2u(a), h2u(b));
        *reinterpret_cast<uint2*>(x16 + (size_t)c*4) = u;
        *reinterpret_cast<uint2*>(sp + h*SP_LD + f4*4) = u;
    }
    __syncthreads();

    int warp = tid >> 5, lane = tid & 31;
    const __half2 ninf2 = __floats2half2_rn(NEG_INF, NEG_INF);

    if (warp < 2) {
        int t = tid;
        __half* d0 = g_dir16[0] + (size_t)plane*HW_;
        __half2 m = ninf2;
        #pragma unroll 8
        for (int h = 0; h < H_; ++h) {
            m = __hmax2(m, *reinterpret_cast<__half2*>(sp + h*SP_LD + 2*t));
            *reinterpret_cast<__half2*>(d0 + h*W_ + 2*t) = m;
        }
    } else if (warp < 4) {
        int t = tid - 64;
        __half* d1 = g_dir16[1] + (size_t)plane*HW_;
        __half2 m = ninf2;
        #pragma unroll 8
        for (int h = H_-1; h >= 0; --h) {
            m = __hmax2(m, *reinterpret_cast<__half2*>(sp + h*SP_LD + 2*t));
            *reinterpret_cast<__half2*>(d1 + h*W_ + 2*t) = m;
        }
    } else {
        __half* d2 = g_dir16[2] + (size_t)plane*HW_;
        __half* d3 = g_dir16[3] + (size_t)plane*HW_;
        for (int r = 0; r < 32; ++r) {
            int h = (warp - 4)*32 + r;
            uint2 u = *reinterpret_cast<uint2*>(sp + h*SP_LD + 4*lane);
            float2 f0 = __half22float2(*reinterpret_cast<__half2*>(&u.x));
            float2 f1 = __half22float2(*reinterpret_cast<__half2*>(&u.y));
            float v0 = f0.x, v1 = f0.y, v2 = f1.x, v3 = f1.y;

            float p0 = v0, p1 = fmaxf(v1,p0), p2 = fmaxf(v2,p1), p3 = fmaxf(v3,p2);
            float agg = p3;
            #pragma unroll
            for (int d = 1; d < 32; d <<= 1) {
                float t = __shfl_up_sync(0xffffffffu, agg, d);
                if (lane >= d) agg = fmaxf(agg, t);
            }
            float prev = __shfl_up_sync(0xffffffffu, agg, 1);
            if (lane == 0) prev = NEG_INF;
            __half2 P01 = __floats2half2_rn(fmaxf(p0,prev), fmaxf(p1,prev));
            __half2 P23 = __floats2half2_rn(fmaxf(p2,prev), fmaxf(p3,prev));
            *reinterpret_cast<uint2*>(d2 + h*W_ + 4*lane) =
                make_uint2(h2u(P01), h2u(P23));

            float s3 = v3, s2 = fmaxf(v2,s3), s1 = fmaxf(v1,s2), s0 = fmaxf(v0,s1);
            float agg2 = s0;
            #pragma unroll
            for (int d = 1; d < 32; d <<= 1) {
                float t = __shfl_down_sync(0xffffffffu, agg2, d);
                if (lane + d < 32) agg2 = fmaxf(agg2, t);
            }
            float nxt = __shfl_down_sync(0xffffffffu, agg2, 1);
            if (lane == 31) nxt = NEG_INF;
            __half2 S01 = __floats2half2_rn(fmaxf(s0,nxt), fmaxf(s1,nxt));
            __half2 S23 = __floats2half2_rn(fmaxf(s2,nxt), fmaxf(s3,nxt));
            *reinterpret_cast<uint2*>(d3 + h*W_ + 4*lane) =
                make_uint2(h2u(S01), h2u(S23));
        }
    }
}

// ------------------------------------------------------------------
// kernel 2: fp16 GEMM, 2 CTAs/SM. BM=128 pixels, BN=128 outs per CTA,
// BK=32, 256 threads, warp tile 64x32 (2x4 warp grid), 3 stages,
// per-phase fragment loads (register budget <= 128 for occupancy 2).
// Grid (128, 2, 8): y = O-half (adjacent pairs share A via L2).
// ------------------------------------------------------------------
#define BM 128
#define BN 128
#define BK 32
#define STAGES 3
#define SA_LD 136
#define SB_LD 136
#define STG_HALVES (BK*SA_LD + BK*SB_LD)
#define GEMM_SMEM (STAGES*STG_HALVES*2)   // 52224 B

__global__ void __launch_bounds__(256, 2) k_gemm(const float* __restrict__ bias,
                                                 float* __restrict__ out) {
    extern __shared__ __half sm[];

    int tid  = threadIdx.x;
    int lane = tid & 31, warp = tid >> 5;
    int wm = warp >> 2, wn = warp & 3;       // 2 x 4 warp grid -> 64x32 warp tiles
    int grp = lane >> 2, tig = lane & 3;
    int lr = lane & 7, lg = lane >> 3;

    int pixbase = blockIdx.x * BM;
    int obase   = blockIdx.y * BN;
    int b       = blockIdx.z;

    size_t boff = (size_t)b * C_ * HW_;
    const __half* srcs[5] = { g_x16 + boff, g_dir16[0] + boff, g_dir16[1] + boff,
                              g_dir16[2] + boff, g_dir16[3] + boff };

    auto load_tile = [&](int kt, int st) {
        int region = kt >> 3;
        int c0 = (kt & 7) * BK;
        const __half* aptr = srcs[region] + (size_t)c0*HW_ + pixbase;
        const __half* bptr = g_wT16 + (size_t)(kt*BK)*O_ + obase;
        __half* sa = sm + st*STG_HALVES;
        __half* sb = sa + BK*SA_LD;
        #pragma unroll
        for (int i = 0; i < 2; ++i) {         // A: 32 rows x 256B = 512 chunks
            int c  = tid + i*256;
            int kr = c >> 4, cc = c & 15;
            cp16(smem_u32(sa + kr*SA_LD + cc*8), aptr + (size_t)kr*HW_ + cc*8);
        }
        #pragma unroll
        for (int i = 0; i < 2; ++i) {         // B: 32 rows x 256B = 512 chunks
            int c  = tid + i*256;
            int kr = c >> 4, cc = c & 15;
            cp16(smem_u32(sb + kr*SB_LD + cc*8), bptr + kr*O_ + cc*8);
        }
        asm volatile("cp.async.commit_group;\n" ::: "memory");
    };

    float acc[4][4][4];
    #pragma unroll
    for (int i = 0; i < 4; ++i)
        #pragma unroll
        for (int j = 0; j < 4; ++j)
            #pragma unroll
            for (int r = 0; r < 4; ++r) acc[i][j][r] = 0.f;

    load_tile(0, 0);
    load_tile(1, 1);

    for (int kt = 0; kt < 40; ++kt) {
        int cur = kt % STAGES;
        if (kt + 2 < 40) {
            load_tile(kt + 2, (kt + 2) % STAGES);
            asm volatile("cp.async.wait_group 2;\n" ::: "memory");
        } else {
            asm volatile("cp.async.wait_group %0;\n" :: "n"(0) : "memory");
        }
        __syncthreads();

        uint32_t saU = smem_u32(sm + cur*STG_HALVES);
        uint32_t sbU = saU + BK*SA_LD*2;

        #pragma unroll
        for (int s = 0; s < 2; ++s) {
            int k0 = s*16;
            uint32_t af[4][4];
            {
                int krow = k0 + lr + ((lg & 2) << 2);
                int cofs = (lg & 1) << 3;
                #pragma unroll
                for (int mf = 0; mf < 4; ++mf) {
                    int m0 = wm*64 + mf*16;
                    uint32_t a = saU + (uint32_t)(krow*SA_LD + m0 + cofs)*2;
                    ldsm_x4_t(af[mf][0], af[mf][1], af[mf][2], af[mf][3], a);
                }
            }
            uint32_t bf[4][2];
            {
                int krow = k0 + lr + ((lg & 1) << 3);
                int cofs = (lg >> 1) << 3;
                #pragma unroll
                for (int jp = 0; jp < 2; ++jp) {
                    int nj = wn*32 + jp*16;
                    uint32_t a = sbU + (uint32_t)(krow*SB_LD + nj + cofs)*2;
                    ldsm_x4_t(bf[2*jp][0], bf[2*jp][1],
                              bf[2*jp+1][0], bf[2*jp+1][1], a);
                }
            }
            #pragma unroll
            for (int mf = 0; mf < 4; ++mf)
                #pragma unroll
                for (int nf = 0; nf < 4; ++nf)
                    mma_f16(acc[mf][nf], af[mf], bf[nf]);
        }
        __syncthreads();
    }

    // epilogue: +bias, store fp32
    float* outb = out + (size_t)b * O_ * HW_;
    #pragma unroll
    for (int nf = 0; nf < 4; ++nf) {
        int o = obase + wn*32 + nf*8 + tig*2;
        float bv0 = bias[o], bv1 = bias[o+1];
        #pragma unroll
        for (int mf = 0; mf < 4; ++mf) {
            int m = pixbase + wm*64 + mf*16 + grp;
            outb[(size_t)o*HW_ + m]         = acc[mf][nf][0] + bv0;
            outb[(size_t)(o+1)*HW_ + m]     = acc[mf][nf][1] + bv1;
            outb[(size_t)o*HW_ + m + 8]     = acc[mf][nf][2] + bv0;
            outb[(size_t)(o+1)*HW_ + m + 8] = acc[mf][nf][3] + bv1;
        }
    }
}

// ------------------------------------------------------------------
// launch: 3 serial launches (R12-proven structure).
// ------------------------------------------------------------------
extern "C" void kernel_launch(void* const* d_in, const int* in_sizes, int n_in,
                              void* d_out, int out_size) {
    (void)in_sizes; (void)n_in; (void)out_size;
    const float* x    = (const float*)d_in[0];
    const float* w    = (const float*)d_in[1];
    const float* bias = (const float*)d_in[2];
    float* out = (float*)d_out;

    cudaFuncSetAttribute(k_gemm, cudaFuncAttributeMaxDynamicSharedMemorySize, GEMM_SMEM);

    k_wt<<<(K_*O_ + 255)/256, 256>>>(w);
    k_dir<<<NPLANE, 256>>>(x);

    dim3 grid(HW_/BM, O_/BN, B_);   // (128, 2, 8)
    k_gemm<<<grid, 256, GEMM_SMEM>>>(bias, out);
}

// round 16
// speedup vs baseline: 1.5023x; 1.0100x over previous
#include <cuda_runtime.h>
#include <cuda_fp16.h>
#include <cstdint>

#define B_ 8
#define C_ 256
#define H_ 128
#define W_ 128
#define HW_ (H_*W_)            // 16384
#define NPLANE (B_*C_)         // 2048
#define K_ 1280
#define O_ 256

#define NEG_INF __int_as_float(0xff800000)

// fp16 scratch: x copy + 4 directional-max tensors + transposed weights.
__device__ __half g_x16[NPLANE*HW_];
__device__ __half g_dir16[4][NPLANE*HW_];
__device__ __half g_wT16[K_*O_];

// ------------------------------------------------------------------
// helpers
// ------------------------------------------------------------------
__device__ __forceinline__ uint32_t smem_u32(const void* p) {
    return (uint32_t)__cvta_generic_to_shared(p);
}
__device__ __forceinline__ void cp16(uint32_t s, const void* g) {
    asm volatile("cp.async.cg.shared.global [%0], [%1], 16;\n" :: "r"(s), "l"(g));
}
__device__ __forceinline__ void ldsm_x4_t(uint32_t& d0, uint32_t& d1,
                                          uint32_t& d2, uint32_t& d3, uint32_t a) {
    asm volatile("ldmatrix.sync.aligned.m8n8.x4.trans.shared.b16 {%0,%1,%2,%3},[%4];\n"
                 : "=r"(d0), "=r"(d1), "=r"(d2), "=r"(d3) : "r"(a));
}
__device__ __forceinline__ void mma_f16(float* d, const uint32_t* a, const uint32_t* b) {
    asm volatile(
        "mma.sync.aligned.m16n8k16.row.col.f32.f16.f16.f32 "
        "{%0,%1,%2,%3},{%4,%5,%6,%7},{%8,%9},{%0,%1,%2,%3};"
        : "+f"(d[0]), "+f"(d[1]), "+f"(d[2]), "+f"(d[3])
        : "r"(a[0]), "r"(a[1]), "r"(a[2]), "r"(a[3]), "r"(b[0]), "r"(b[1]));
}
__device__ __forceinline__ uint32_t h2u(__half2 h) {
    return *reinterpret_cast<uint32_t*>(&h);
}

// ------------------------------------------------------------------
// kernel 0: transpose conv_w [O][K] -> wT16 [K][O]
// ------------------------------------------------------------------
__global__ void k_wt(const float* __restrict__ w) {
    int idx = blockIdx.x * 256 + threadIdx.x;
    if (idx < K_*O_) {
        int o = idx / K_;
        int k = idx - o*K_;
        g_wT16[k*O_ + o] = __float2half_rn(w[idx]);
    }
}

// ------------------------------------------------------------------
// kernel 1: all 4 directional maxes + x16, one plane per CTA, full grid
// (R12/R15-proven: fp16 plane in smem; warps 0-1 H-prefix, 2-3 H-suffix,
//  4-7 W-scans; plain stores).
// ------------------------------------------------------------------
#define SP_LD 132   // halves per smem row (264B)

__global__ void __launch_bounds__(256) k_dir(const float* __restrict__ x) {
    __shared__ __half sp[H_*SP_LD];
    int plane = blockIdx.x;
    const float* src = x + (size_t)plane*HW_;
    __half* x16 = g_x16 + (size_t)plane*HW_;
    int tid = threadIdx.x;

    #pragma unroll
    for (int i = 0; i < 16; ++i) {
        int c = tid + i*256;               // float4 index 0..4095
        int h = c >> 5, f4 = c & 31;
        float4 v = __ldg(reinterpret_cast<const float4*>(src) + c);
        __half2 a = __floats2half2_rn(v.x, v.y);
        __half2 b = __floats2half2_rn(v.z, v.w);
        uint2 u = make_uint2(h2u(a), h2u(b));
        *reinterpret_cast<uint2*>(x16 + (size_t)c*4) = u;
        *reinterpret_cast<uint2*>(sp + h*SP_LD + f4*4) = u;
    }
    __syncthreads();

    int warp = tid >> 5, lane = tid & 31;
    const __half2 ninf2 = __floats2half2_rn(NEG_INF, NEG_INF);

    if (warp < 2) {
        int t = tid;
        __half* d0 = g_dir16[0] + (size_t)plane*HW_;
        __half2 m = ninf2;
        #pragma unroll 8
        for (int h = 0; h < H_; ++h) {
            m = __hmax2(m, *reinterpret_cast<__half2*>(sp + h*SP_LD + 2*t));
            *reinterpret_cast<__half2*>(d0 + h*W_ + 2*t) = m;
        }
    } else if (warp < 4) {
        int t = tid - 64;
        __half* d1 = g_dir16[1] + (size_t)plane*HW_;
        __half2 m = ninf2;
        #pragma unroll 8
        for (int h = H_-1; h >= 0; --h) {
            m = __hmax2(m, *reinterpret_cast<__half2*>(sp + h*SP_LD + 2*t));
            *reinterpret_cast<__half2*>(d1 + h*W_ + 2*t) = m;
        }
    } else {
        __half* d2 = g_dir16[2] + (size_t)plane*HW_;
        __half* d3 = g_dir16[3] + (size_t)plane*HW_;
        for (int r = 0; r < 32; ++r) {
            int h = (warp - 4)*32 + r;
            uint2 u = *reinterpret_cast<uint2*>(sp + h*SP_LD + 4*lane);
            float2 f0 = __half22float2(*reinterpret_cast<__half2*>(&u.x));
            float2 f1 = __half22float2(*reinterpret_cast<__half2*>(&u.y));
            float v0 = f0.x, v1 = f0.y, v2 = f1.x, v3 = f1.y;

            float p0 = v0, p1 = fmaxf(v1,p0), p2 = fmaxf(v2,p1), p3 = fmaxf(v3,p2);
            float agg = p3;
            #pragma unroll
            for (int d = 1; d < 32; d <<= 1) {
                float t = __shfl_up_sync(0xffffffffu, agg, d);
                if (lane >= d) agg = fmaxf(agg, t);
            }
            float prev = __shfl_up_sync(0xffffffffu, agg, 1);
            if (lane == 0) prev = NEG_INF;
            __half2 P01 = __floats2half2_rn(fmaxf(p0,prev), fmaxf(p1,prev));
            __half2 P23 = __floats2half2_rn(fmaxf(p2,prev), fmaxf(p3,prev));
            *reinterpret_cast<uint2*>(d2 + h*W_ + 4*lane) =
                make_uint2(h2u(P01), h2u(P23));

            float s3 = v3, s2 = fmaxf(v2,s3), s1 = fmaxf(v1,s2), s0 = fmaxf(v0,s1);
            float agg2 = s0;
            #pragma unroll
            for (int d = 1; d < 32; d <<= 1) {
                float t = __shfl_down_sync(0xffffffffu, agg2, d);
                if (lane + d < 32) agg2 = fmaxf(agg2, t);
            }
            float nxt = __shfl_down_sync(0xffffffffu, agg2, 1);
            if (lane == 31) nxt = NEG_INF;
            __half2 S01 = __floats2half2_rn(fmaxf(s0,nxt), fmaxf(s1,nxt));
            __half2 S23 = __floats2half2_rn(fmaxf(s2,nxt), fmaxf(s3,nxt));
            *reinterpret_cast<uint2*>(d3 + h*W_ + 4*lane) =
                make_uint2(h2u(S01), h2u(S23));
        }
    }
}

// ------------------------------------------------------------------
// kernel 2: fp16 GEMM, 2 CTAs/SM. BM=128 pixels, BN=128 outs per CTA,
// BK=32, 256 threads, warp tile 64x32, 4 stages (deeper DRAM cushion).
// Grid (128, 2, 8): y = O-half (adjacent pairs share A via L2).
// ------------------------------------------------------------------
#define BM 128
#define BN 128
#define BK 32
#define STAGES 4
#define SA_LD 136
#define SB_LD 136
#define STG_HALVES (BK*SA_LD + BK*SB_LD)
#define GEMM_SMEM (STAGES*STG_HALVES*2)   // 69632 B (2 CTAs = 139264 <= 228KB)

__global__ void __launch_bounds__(256, 2) k_gemm(const float* __restrict__ bias,
                                                 float* __restrict__ out) {
    extern __shared__ __half sm[];

    int tid  = threadIdx.x;
    int lane = tid & 31, warp = tid >> 5;
    int wm = warp >> 2, wn = warp & 3;       // 2 x 4 warp grid -> 64x32 warp tiles
    int grp = lane >> 2, tig = lane & 3;
    int lr = lane & 7, lg = lane >> 3;

    int pixbase = blockIdx.x * BM;
    int obase   = blockIdx.y * BN;
    int b       = blockIdx.z;

    size_t boff = (size_t)b * C_ * HW_;
    const __half* srcs[5] = { g_x16 + boff, g_dir16[0] + boff, g_dir16[1] + boff,
                              g_dir16[2] + boff, g_dir16[3] + boff };

    auto load_tile = [&](int kt, int st) {
        int region = kt >> 3;
        int c0 = (kt & 7) * BK;
        const __half* aptr = srcs[region] + (size_t)c0*HW_ + pixbase;
        const __half* bptr = g_wT16 + (size_t)(kt*BK)*O_ + obase;
        __half* sa = sm + st*STG_HALVES;
        __half* sb = sa + BK*SA_LD;
        #pragma unroll
        for (int i = 0; i < 2; ++i) {         // A: 32 rows x 256B
            int c  = tid + i*256;
            int kr = c >> 4, cc = c & 15;
            cp16(smem_u32(sa + kr*SA_LD + cc*8), aptr + (size_t)kr*HW_ + cc*8);
        }
        #pragma unroll
        for (int i = 0; i < 2; ++i) {         // B: 32 rows x 256B
            int c  = tid + i*256;
            int kr = c >> 4, cc = c & 15;
            cp16(smem_u32(sb + kr*SB_LD + cc*8), bptr + kr*O_ + cc*8);
        }
        asm volatile("cp.async.commit_group;\n" ::: "memory");
    };

    float acc[4][4][4];
    #pragma unroll
    for (int i = 0; i < 4; ++i)
        #pragma unroll
        for (int j = 0; j < 4; ++j)
            #pragma unroll
            for (int r = 0; r < 4; ++r) acc[i][j][r] = 0.f;

    load_tile(0, 0);
    load_tile(1, 1);
    load_tile(2, 2);

    for (int kt = 0; kt < 40; ++kt) {
        int cur = kt % STAGES;
        if (kt + 3 < 40) {
            load_tile(kt + 3, (kt + 3) % STAGES);
            asm volatile("cp.async.wait_group 3;\n" ::: "memory");
        } else if (kt == 37) {
            asm volatile("cp.async.wait_group 2;\n" ::: "memory");
        } else if (kt == 38) {
            asm volatile("cp.async.wait_group 1;\n" ::: "memory");
        } else {
            asm volatile("cp.async.wait_group 0;\n" ::: "memory");
        }
        __syncthreads();

        uint32_t saU = smem_u32(sm + cur*STG_HALVES);
        uint32_t sbU = saU + BK*SA_LD*2;

        #pragma unroll
        for (int s = 0; s < 2; ++s) {
            int k0 = s*16;
            uint32_t af[4][4];
            {
                int krow = k0 + lr + ((lg & 2) << 2);
                int cofs = (lg & 1) << 3;
                #pragma unroll
                for (int mf = 0; mf < 4; ++mf) {
                    int m0 = wm*64 + mf*16;
                    uint32_t a = saU + (uint32_t)(krow*SA_LD + m0 + cofs)*2;
                    ldsm_x4_t(af[mf][0], af[mf][1], af[mf][2], af[mf][3], a);
                }
            }
            uint32_t bf[4][2];
            {
                int krow = k0 + lr + ((lg & 1) << 3);
                int cofs = (lg >> 1) << 3;
                #pragma unroll
                for (int jp = 0; jp < 2; ++jp) {
                    int nj = wn*32 + jp*16;
                    uint32_t a = sbU + (uint32_t)(krow*SB_LD + nj + cofs)*2;
                    ldsm_x4_t(bf[2*jp][0], bf[2*jp][1],
                              bf[2*jp+1][0], bf[2*jp+1][1], a);
                }
            }
            #pragma unroll
            for (int mf = 0; mf < 4; ++mf)
                #pragma unroll
                for (int nf = 0; nf < 4; ++nf)
                    mma_f16(acc[mf][nf], af[mf], bf[nf]);
        }
        __syncthreads();
    }

    // epilogue: +bias, store fp32
    float* outb = out + (size_t)b * O_ * HW_;
    #pragma unroll
    for (int nf = 0; nf < 4; ++nf) {
        int o = obase + wn*32 + nf*8 + tig*2;
        float bv0 = bias[o], bv1 = bias[o+1];
        #pragma unroll
        for (int mf = 0; mf < 4; ++mf) {
            int m = pixbase + wm*64 + mf*16 + grp;
            outb[(size_t)o*HW_ + m]         = acc[mf][nf][0] + bv0;
            outb[(size_t)(o+1)*HW_ + m]     = acc[mf][nf][1] + bv1;
            outb[(size_t)o*HW_ + m + 8]     = acc[mf][nf][2] + bv0;
            outb[(size_t)(o+1)*HW_ + m + 8] = acc[mf][nf][3] + bv1;
        }
    }
}

// ------------------------------------------------------------------
// launch: k_wt overlapped on a side stream (2 streams / 2 events total,
// guard-safe per R7/R13); dir then gemm on the capture stream.
// ------------------------------------------------------------------
extern "C" void kernel_launch(void* const* d_in, const int* in_sizes, int n_in,
                              void* d_out, int out_size) {
    (void)in_sizes; (void)n_in; (void)out_size;
    const float* x    = (const float*)d_in[0];
    const float* w    = (const float*)d_in[1];
    const float* bias = (const float*)d_in[2];
    float* out = (float*)d_out;

    static cudaStream_t sW = nullptr;
    static cudaEvent_t evFork, evW;
    if (!sW) {
        cudaStreamCreateWithFlags(&sW, cudaStreamNonBlocking);
        cudaEventCreateWithFlags(&evFork, cudaEventDisableTiming);
        cudaEventCreateWithFlags(&evW,    cudaEventDisableTiming);
        cudaFuncSetAttribute(k_gemm, cudaFuncAttributeMaxDynamicSharedMemorySize, GEMM_SMEM);
    }

    cudaEventRecord(evFork, 0);
    cudaStreamWaitEvent(sW, evFork, 0);
    k_wt<<<(K_*O_ + 255)/256, 256, 0, sW>>>(w);
    cudaEventRecord(evW, sW);

    k_dir<<<NPLANE, 256>>>(x);

    cudaStreamWaitEvent(0, evW, 0);
    dim3 grid(HW_/BM, O_/BN, B_);   // (128, 2, 8)
    k_gemm<<<grid, 256, GEMM_SMEM>>>(bias, out);
}